// round 4
// baseline (speedup 1.0000x reference)
#include <cuda_runtime.h>
#include <math.h>

// ---------------- problem constants ----------------
#define CDIM 128
#define NTOT 260000
#define MAXN 120000
#define OUTD 10

// rank sizes and nnz (fixed by the problem)
__host__ __device__ static const int kNR[4] = {40000, 120000, 80000, 20000};
static const int kADJ[4] = {320000, 960000, 640000, 160000};
static const int kINC[3] = {240000, 240000, 80000};
static const int kOFF[4] = {0, 40000, 160000, 240000};

// ---------------- device scratch (static, sanctioned) ----------------
__device__ float g_xa[(size_t)NTOT * CDIM];   // layer-0 output (all ranks concat)
__device__ float g_xb[(size_t)NTOT * CDIM];   // layer-1 output
__device__ float g_t [(size_t)MAXN * CDIM];   // transformed features (x @ W)
__device__ float g_m [(size_t)MAXN * CDIM];   // message accumulator

// ---------------- kernels ----------------

__global__ void zero_f4(float4* __restrict__ p, int n4) {
    int i = blockIdx.x * blockDim.x + threadIdx.x;
    if (i < n4) p[i] = make_float4(0.f, 0.f, 0.f, 0.f);
}

// C[M,128] = A[M,128] @ B[128,128], fp32 SIMT SGEMM.
// 128x128 block tile, BK=8, 256 threads, 8x8 microtile per thread.
__global__ __launch_bounds__(256) void gemm128(const float* __restrict__ A,
                                               const float* __restrict__ B,
                                               float* __restrict__ Cc, int M) {
    __shared__ float As[8][128];
    __shared__ float Bs[8][128];
    const int tid = threadIdx.x;
    const int tx = tid & 15;
    const int ty = tid >> 4;
    const int rowBase = blockIdx.x * 128;
    const int lm = tid >> 1;            // 0..127 : tile row loaded by this thread
    const int lk = (tid & 1) * 4;       // 0 or 4 : k-offset within BK chunk
    const int bk = tid >> 5;            // 0..7
    const int bn = (tid & 31) * 4;      // 0..124

    float acc[8][8];
#pragma unroll
    for (int i = 0; i < 8; i++)
#pragma unroll
        for (int j = 0; j < 8; j++) acc[i][j] = 0.f;

    const int arow = rowBase + lm;
    for (int k0 = 0; k0 < 128; k0 += 8) {
        float4 av = make_float4(0.f, 0.f, 0.f, 0.f);
        if (arow < M) av = *(const float4*)(A + (size_t)arow * 128 + k0 + lk);
        As[lk + 0][lm] = av.x; As[lk + 1][lm] = av.y;
        As[lk + 2][lm] = av.z; As[lk + 3][lm] = av.w;
        *(float4*)&Bs[bk][bn] = *(const float4*)(B + (size_t)(k0 + bk) * 128 + bn);
        __syncthreads();
#pragma unroll
        for (int kk = 0; kk < 8; kk++) {
            float4 a0 = *(const float4*)&As[kk][ty * 8];
            float4 a1 = *(const float4*)&As[kk][ty * 8 + 4];
            float4 b0 = *(const float4*)&Bs[kk][tx * 8];
            float4 b1 = *(const float4*)&Bs[kk][tx * 8 + 4];
            float a[8] = {a0.x, a0.y, a0.z, a0.w, a1.x, a1.y, a1.z, a1.w};
            float b[8] = {b0.x, b0.y, b0.z, b0.w, b1.x, b1.y, b1.z, b1.w};
#pragma unroll
            for (int i = 0; i < 8; i++)
#pragma unroll
                for (int j = 0; j < 8; j++) acc[i][j] = fmaf(a[i], b[j], acc[i][j]);
        }
        __syncthreads();
    }
#pragma unroll
    for (int i = 0; i < 8; i++) {
        int grow = rowBase + ty * 8 + i;
        if (grow < M) {
            float4 v0 = make_float4(acc[i][0], acc[i][1], acc[i][2], acc[i][3]);
            float4 v1 = make_float4(acc[i][4], acc[i][5], acc[i][6], acc[i][7]);
            *(float4*)(Cc + (size_t)grow * 128 + tx * 8) = v0;
            *(float4*)(Cc + (size_t)grow * 128 + tx * 8 + 4) = v1;
        }
    }
}

// m[row[e]] += val[e] * t[col[e]]  (one warp per edge, vector f32 reduction)
__global__ void spmm_edge(const int* __restrict__ rows, const int* __restrict__ cols,
                          const float* __restrict__ vals, const float* __restrict__ t,
                          float* __restrict__ m, int nnz) {
    int g = blockIdx.x * blockDim.x + threadIdx.x;
    int gw = g >> 5;
    if (gw >= nnz) return;
    int lane = g & 31;
    int r = rows[gw];
    int c = cols[gw];
    float v = vals[gw];
    float4 a = *(const float4*)(t + (size_t)c * 128 + lane * 4);
    float* dst = m + (size_t)r * 128 + lane * 4;
    asm volatile("red.global.add.v4.f32 [%0], {%1,%2,%3,%4};"
                 :: "l"(dst), "f"(a.x * v), "f"(a.y * v), "f"(a.z * v), "f"(a.w * v)
                 : "memory");
}

__global__ void sigmoid_f4(const float4* __restrict__ in, float4* __restrict__ out, int n4) {
    int i = blockIdx.x * blockDim.x + threadIdx.x;
    if (i >= n4) return;
    float4 v = in[i];
    v.x = 1.f / (1.f + expf(-v.x));
    v.y = 1.f / (1.f + expf(-v.y));
    v.z = 1.f / (1.f + expf(-v.z));
    v.w = 1.f / (1.f + expf(-v.w));
    out[i] = v;
}

// out[M,10] = softmax(x[M,128] @ W[128,10] + b)  — one warp per row
__global__ __launch_bounds__(256) void head_kernel(const float* __restrict__ x,
                                                   const float* __restrict__ W,
                                                   const float* __restrict__ b,
                                                   float* __restrict__ out, int M) {
    __shared__ float Ws[128 * OUTD];
    __shared__ float bs[OUTD];
    int tid = threadIdx.x;
    for (int i = tid; i < 128 * OUTD; i += 256) Ws[i] = W[i];
    if (tid < OUTD) bs[tid] = b[tid];
    __syncthreads();
    int lane = tid & 31;
    int row = blockIdx.x * 8 + (tid >> 5);
    if (row >= M) return;
    float xv[4];
#pragma unroll
    for (int q = 0; q < 4; q++) xv[q] = x[(size_t)row * 128 + q * 32 + lane];
    float e[OUTD];
    float mx = -1e30f;
#pragma unroll
    for (int j = 0; j < OUTD; j++) {
        float p = 0.f;
#pragma unroll
        for (int q = 0; q < 4; q++) p = fmaf(xv[q], Ws[(q * 32 + lane) * OUTD + j], p);
#pragma unroll
        for (int s = 16; s; s >>= 1) p += __shfl_xor_sync(0xffffffffu, p, s);
        e[j] = p + bs[j];
        mx = fmaxf(mx, e[j]);
    }
    float sum = 0.f;
#pragma unroll
    for (int j = 0; j < OUTD; j++) { e[j] = expf(e[j] - mx); sum += e[j]; }
    if (lane == 0) {
        float inv = 1.f / sum;
#pragma unroll
        for (int j = 0; j < OUTD; j++) out[(size_t)row * OUTD + j] = e[j] * inv;
    }
}

// ---------------- launch ----------------
extern "C" void kernel_launch(void* const* d_in, const int* in_sizes, int n_in,
                              void* d_out, int out_size) {
    (void)in_sizes; (void)n_in; (void)out_size;

    const int* adj_row[4]; const int* adj_col[4]; const float* adj_val[4];
    for (int r = 0; r < 4; r++) {
        adj_row[r] = (const int*)d_in[4 + 3 * r];
        adj_col[r] = (const int*)d_in[5 + 3 * r];
        adj_val[r] = (const float*)d_in[6 + 3 * r];
    }
    const int* inc_row[3]; const int* inc_col[3]; const float* inc_val[3];
    for (int i = 0; i < 3; i++) {
        inc_row[i] = (const int*)d_in[16 + 3 * i];
        inc_col[i] = (const int*)d_in[17 + 3 * i];
        inc_val[i] = (const float*)d_in[18 + 3 * i];
    }
    const float* W_same = (const float*)d_in[25];  // [2,4,128,128]
    const float* W_h2l  = (const float*)d_in[26];  // [2,3,128,128]
    const float* W_l2h  = (const float*)d_in[27];  // [2,3,128,128]
    const float* W_out  = (const float*)d_in[28];  // [128,10]
    const float* b_out  = (const float*)d_in[29];  // [10]

    float *xa, *xb, *t, *m;
    cudaGetSymbolAddress((void**)&xa, g_xa);
    cudaGetSymbolAddress((void**)&xb, g_xb);
    cudaGetSymbolAddress((void**)&t,  g_t);
    cudaGetSymbolAddress((void**)&m,  g_m);

    const size_t WSZ = (size_t)CDIM * CDIM;

    for (int l = 0; l < 2; l++) {
        const float* cur[4];
        float* nxt = (l == 0) ? xa : xb;
        for (int rr = 0; rr < 4; rr++)
            cur[rr] = (l == 0) ? (const float*)d_in[rr] : (xa + (size_t)kOFF[rr] * CDIM);

        for (int r = 0; r < 4; r++) {
            int n4 = kNR[r] * (CDIM / 4);
            zero_f4<<<(n4 + 255) / 256, 256>>>((float4*)m, n4);

            // same-rank adjacency message
            gemm128<<<(kNR[r] + 127) / 128, 256>>>(cur[r], W_same + (size_t)(l * 4 + r) * WSZ, t, kNR[r]);
            spmm_edge<<<(kADJ[r] * 32 + 255) / 256, 256>>>(adj_row[r], adj_col[r], adj_val[r], t, m, kADJ[r]);

            // high-to-low: inc_{r+1} @ (x_{r+1} W_h2l)
            if (r < 3) {
                gemm128<<<(kNR[r + 1] + 127) / 128, 256>>>(cur[r + 1], W_h2l + (size_t)(l * 3 + r) * WSZ, t, kNR[r + 1]);
                spmm_edge<<<(kINC[r] * 32 + 255) / 256, 256>>>(inc_row[r], inc_col[r], inc_val[r], t, m, kINC[r]);
            }
            // low-to-high: inc_r^T @ (x_{r-1} W_l2h)
            if (r > 0) {
                gemm128<<<(kNR[r - 1] + 127) / 128, 256>>>(cur[r - 1], W_l2h + (size_t)(l * 3 + r - 1) * WSZ, t, kNR[r - 1]);
                spmm_edge<<<(kINC[r - 1] * 32 + 255) / 256, 256>>>(inc_col[r - 1], inc_row[r - 1], inc_val[r - 1], t, m, kINC[r - 1]);
            }

            sigmoid_f4<<<(n4 + 255) / 256, 256>>>((const float4*)m, (float4*)(nxt + (size_t)kOFF[r] * CDIM), n4);
        }
    }

    head_kernel<<<(kNR[0] + 7) / 8, 256>>>(xb + (size_t)kOFF[0] * CDIM, W_out, b_out, (float*)d_out, kNR[0]);
}

// round 7
// speedup vs baseline: 2.3434x; 2.3434x over previous
#include <cuda_runtime.h>
#include <math.h>

// ---------------- problem constants ----------------
#define CDIM 128
#define NTOT 260000
#define MAXN 120000
#define OUTD 10

__host__ __device__ static const int kNR[4] = {40000, 120000, 80000, 20000};
static const int kADJ[4] = {320000, 960000, 640000, 160000};
static const int kINC[3] = {240000, 240000, 80000};
static const int kOFF[4] = {0, 40000, 160000, 240000};

// ---------------- device scratch (static, sanctioned) ----------------
__device__ float g_xa[(size_t)NTOT * CDIM];
__device__ float g_xb[(size_t)NTOT * CDIM];
__device__ float g_t [(size_t)MAXN * CDIM];
__device__ float g_m [(size_t)MAXN * CDIM];

// ---------------- kernels ----------------

__global__ void zero_f4(float4* __restrict__ p, int n4) {
    int i = blockIdx.x * blockDim.x + threadIdx.x;
    if (i < n4) p[i] = make_float4(0.f, 0.f, 0.f, 0.f);
}

// ---- tf32 tensor-core GEMM: C[M,128] = A[M,128] @ B[128,128] ----
// Block: 256 threads (8 warps), tile 128(M)x128(N). Warp tile 32x64.
// K chunked by 32, staged in smem with cvt.rna.tf32 at staging time.

__device__ __forceinline__ unsigned f2tf32(float f) {
    unsigned u;
    asm("cvt.rna.tf32.f32 %0, %1;" : "=r"(u) : "f"(f));
    return u;
}

__device__ __forceinline__ void mma_tf32(float* c, const unsigned* a, unsigned b0, unsigned b1) {
    asm volatile(
        "mma.sync.aligned.m16n8k8.row.col.f32.tf32.tf32.f32 "
        "{%0,%1,%2,%3}, {%4,%5,%6,%7}, {%8,%9}, {%0,%1,%2,%3};"
        : "+f"(c[0]), "+f"(c[1]), "+f"(c[2]), "+f"(c[3])
        : "r"(a[0]), "r"(a[1]), "r"(a[2]), "r"(a[3]), "r"(b0), "r"(b1));
}

#define SMS 36  // smem row stride (floats): 32 + 4 pad -> conflict-free frag loads

__global__ __launch_bounds__(256, 2) void gemm_tf32(const float* __restrict__ A,
                                                    const float* __restrict__ B,
                                                    float* __restrict__ Cc, int M) {
    __shared__ unsigned As[128 * SMS];  // row-major [m][k-chunk]
    __shared__ unsigned Bs[128 * SMS];  // n-major   [n][k-chunk]

    const int tid  = threadIdx.x;
    const int wid  = tid >> 5;
    const int lane = tid & 31;
    const int g    = lane >> 2;    // 0..7
    const int t4   = lane & 3;     // 0..3
    const int mbase = (wid >> 1) * 32;   // warp M offset in tile
    const int nbase = (wid & 1) * 64;    // warp N offset in tile
    const int rowBase = blockIdx.x * 128;

    // staging roles
    const int srow = tid >> 1;           // 0..127  (A row / B col)
    const int skq  = (tid & 1) * 16;     // 0 or 16 (k quarter)
    const int arow = rowBase + srow;
    const bool arow_ok = (arow < M);

    float acc[2][8][4];
#pragma unroll
    for (int mi = 0; mi < 2; mi++)
#pragma unroll
        for (int ni = 0; ni < 8; ni++)
#pragma unroll
            for (int q = 0; q < 4; q++) acc[mi][ni][q] = 0.f;

    for (int c = 0; c < 4; ++c) {
        const int K0 = c * 32;
        // ---- stage A chunk: rows srow, k [K0+skq, +16) ----
#pragma unroll
        for (int j = 0; j < 4; j++) {
            float4 v = make_float4(0.f, 0.f, 0.f, 0.f);
            if (arow_ok)
                v = *(const float4*)(A + (size_t)arow * 128 + K0 + skq + j * 4);
            unsigned* dst = &As[srow * SMS + skq + j * 4];
            dst[0] = f2tf32(v.x); dst[1] = f2tf32(v.y);
            dst[2] = f2tf32(v.z); dst[3] = f2tf32(v.w);
        }
        // ---- stage B chunk transposed: col srow, k [K0+skq, +16) ----
#pragma unroll
        for (int j = 0; j < 16; j++) {
            float bv = B[(size_t)(K0 + skq + j) * 128 + srow];
            Bs[srow * SMS + skq + j] = f2tf32(bv);
        }
        __syncthreads();

        // ---- compute 4 k-steps of 8 ----
#pragma unroll
        for (int kt = 0; kt < 4; kt++) {
            const int kk = kt * 8;
            unsigned a[2][4];
#pragma unroll
            for (int mi = 0; mi < 2; mi++) {
                int r0 = (mbase + mi * 16 + g) * SMS + kk + t4;
                a[mi][0] = As[r0];
                a[mi][1] = As[r0 + 8 * SMS];
                a[mi][2] = As[r0 + 4];
                a[mi][3] = As[r0 + 8 * SMS + 4];
            }
#pragma unroll
            for (int ni = 0; ni < 8; ni++) {
                int cb = (nbase + ni * 8 + g) * SMS + kk + t4;
                unsigned b0 = Bs[cb];
                unsigned b1 = Bs[cb + 4];
                mma_tf32(acc[0][ni], a[0], b0, b1);
                mma_tf32(acc[1][ni], a[1], b0, b1);
            }
        }
        __syncthreads();
    }

    // ---- epilogue ----
#pragma unroll
    for (int mi = 0; mi < 2; mi++) {
        int r0 = rowBase + mbase + mi * 16 + g;
        int r1 = r0 + 8;
#pragma unroll
        for (int ni = 0; ni < 8; ni++) {
            int col = nbase + ni * 8 + t4 * 2;
            if (r0 < M)
                *(float2*)(Cc + (size_t)r0 * 128 + col) = make_float2(acc[mi][ni][0], acc[mi][ni][1]);
            if (r1 < M)
                *(float2*)(Cc + (size_t)r1 * 128 + col) = make_float2(acc[mi][ni][2], acc[mi][ni][3]);
        }
    }
}

// m[row[e]] += val[e] * t[col[e]]  (one warp per edge, vector f32 reduction)
__global__ void spmm_edge(const int* __restrict__ rows, const int* __restrict__ cols,
                          const float* __restrict__ vals, const float* __restrict__ t,
                          float* __restrict__ m, int nnz) {
    int g = blockIdx.x * blockDim.x + threadIdx.x;
    int gw = g >> 5;
    if (gw >= nnz) return;
    int lane = g & 31;
    int r = rows[gw];
    int c = cols[gw];
    float v = vals[gw];
    float4 a = *(const float4*)(t + (size_t)c * 128 + lane * 4);
    float* dst = m + (size_t)r * 128 + lane * 4;
    asm volatile("red.global.add.v4.f32 [%0], {%1,%2,%3,%4};"
                 :: "l"(dst), "f"(a.x * v), "f"(a.y * v), "f"(a.z * v), "f"(a.w * v)
                 : "memory");
}

__global__ void sigmoid_f4(const float4* __restrict__ in, float4* __restrict__ out, int n4) {
    int i = blockIdx.x * blockDim.x + threadIdx.x;
    if (i >= n4) return;
    float4 v = in[i];
    v.x = 1.f / (1.f + expf(-v.x));
    v.y = 1.f / (1.f + expf(-v.y));
    v.z = 1.f / (1.f + expf(-v.z));
    v.w = 1.f / (1.f + expf(-v.w));
    out[i] = v;
}

// out[M,10] = softmax(x[M,128] @ W[128,10] + b)  — one warp per row
__global__ __launch_bounds__(256) void head_kernel(const float* __restrict__ x,
                                                   const float* __restrict__ W,
                                                   const float* __restrict__ b,
                                                   float* __restrict__ out, int M) {
    __shared__ float Ws[128 * OUTD];
    __shared__ float bs[OUTD];
    int tid = threadIdx.x;
    for (int i = tid; i < 128 * OUTD; i += 256) Ws[i] = W[i];
    if (tid < OUTD) bs[tid] = b[tid];
    __syncthreads();
    int lane = tid & 31;
    int row = blockIdx.x * 8 + (tid >> 5);
    if (row >= M) return;
    float xv[4];
#pragma unroll
    for (int q = 0; q < 4; q++) xv[q] = x[(size_t)row * 128 + q * 32 + lane];
    float e[OUTD];
    float mx = -1e30f;
#pragma unroll
    for (int j = 0; j < OUTD; j++) {
        float p = 0.f;
#pragma unroll
        for (int q = 0; q < 4; q++) p = fmaf(xv[q], Ws[(q * 32 + lane) * OUTD + j], p);
#pragma unroll
        for (int s = 16; s; s >>= 1) p += __shfl_xor_sync(0xffffffffu, p, s);
        e[j] = p + bs[j];
        mx = fmaxf(mx, e[j]);
    }
    float sum = 0.f;
#pragma unroll
    for (int j = 0; j < OUTD; j++) { e[j] = expf(e[j] - mx); sum += e[j]; }
    if (lane == 0) {
        float inv = 1.f / sum;
#pragma unroll
        for (int j = 0; j < OUTD; j++) out[(size_t)row * OUTD + j] = e[j] * inv;
    }
}

// ---------------- launch ----------------
extern "C" void kernel_launch(void* const* d_in, const int* in_sizes, int n_in,
                              void* d_out, int out_size) {
    (void)in_sizes; (void)n_in; (void)out_size;

    const int* adj_row[4]; const int* adj_col[4]; const float* adj_val[4];
    for (int r = 0; r < 4; r++) {
        adj_row[r] = (const int*)d_in[4 + 3 * r];
        adj_col[r] = (const int*)d_in[5 + 3 * r];
        adj_val[r] = (const float*)d_in[6 + 3 * r];
    }
    const int* inc_row[3]; const int* inc_col[3]; const float* inc_val[3];
    for (int i = 0; i < 3; i++) {
        inc_row[i] = (const int*)d_in[16 + 3 * i];
        inc_col[i] = (const int*)d_in[17 + 3 * i];
        inc_val[i] = (const float*)d_in[18 + 3 * i];
    }
    const float* W_same = (const float*)d_in[25];  // [2,4,128,128]
    const float* W_h2l  = (const float*)d_in[26];  // [2,3,128,128]
    const float* W_l2h  = (const float*)d_in[27];  // [2,3,128,128]
    const float* W_out  = (const float*)d_in[28];  // [128,10]
    const float* b_out  = (const float*)d_in[29];  // [10]

    float *xa, *xb, *t, *m;
    cudaGetSymbolAddress((void**)&xa, g_xa);
    cudaGetSymbolAddress((void**)&xb, g_xb);
    cudaGetSymbolAddress((void**)&t,  g_t);
    cudaGetSymbolAddress((void**)&m,  g_m);

    const size_t WSZ = (size_t)CDIM * CDIM;

    for (int l = 0; l < 2; l++) {
        const float* cur[4];
        float* nxt = (l == 0) ? xa : xb;
        for (int rr = 0; rr < 4; rr++)
            cur[rr] = (l == 0) ? (const float*)d_in[rr] : (xa + (size_t)kOFF[rr] * CDIM);

        for (int r = 0; r < 4; r++) {
            int n4 = kNR[r] * (CDIM / 4);
            zero_f4<<<(n4 + 255) / 256, 256>>>((float4*)m, n4);

            // same-rank adjacency message
            gemm_tf32<<<(kNR[r] + 127) / 128, 256>>>(cur[r], W_same + (size_t)(l * 4 + r) * WSZ, t, kNR[r]);
            spmm_edge<<<(kADJ[r] * 32 + 255) / 256, 256>>>(adj_row[r], adj_col[r], adj_val[r], t, m, kADJ[r]);

            // high-to-low: inc_{r+1} @ (x_{r+1} W_h2l)
            if (r < 3) {
                gemm_tf32<<<(kNR[r + 1] + 127) / 128, 256>>>(cur[r + 1], W_h2l + (size_t)(l * 3 + r) * WSZ, t, kNR[r + 1]);
                spmm_edge<<<(kINC[r] * 32 + 255) / 256, 256>>>(inc_row[r], inc_col[r], inc_val[r], t, m, kINC[r]);
            }
            // low-to-high: inc_r^T @ (x_{r-1} W_l2h)
            if (r > 0) {
                gemm_tf32<<<(kNR[r - 1] + 127) / 128, 256>>>(cur[r - 1], W_l2h + (size_t)(l * 3 + r - 1) * WSZ, t, kNR[r - 1]);
                spmm_edge<<<(kINC[r - 1] * 32 + 255) / 256, 256>>>(inc_col[r - 1], inc_row[r - 1], inc_val[r - 1], t, m, kINC[r - 1]);
            }

            sigmoid_f4<<<(n4 + 255) / 256, 256>>>((const float4*)m, (float4*)(nxt + (size_t)kOFF[r] * CDIM), n4);
        }
    }

    head_kernel<<<(kNR[0] + 7) / 8, 256>>>(xb + (size_t)kOFF[0] * CDIM, W_out, b_out, (float*)d_out, kNR[0]);
}